// round 4
// baseline (speedup 1.0000x reference)
#include <cuda_runtime.h>
#include <cstdint>

// Problem constants
#define Nb   8
#define LQ   2048
#define Cc   256
#define Mh   8
#define Ll   4
#define Pp   4
#define DH   32
#define Ssum 3840           // sum of LENS
#define NQ   (Nb*LQ)        // 16384
#define NROWS_VAL (Nb*Ssum) // 30720

// Static per-level lengths / starts (reference treats these as static constants;
// setup_inputs fixes them). Avoids any int64-vs-int32 harness dtype ambiguity.
__device__ __constant__ int c_T[4]     = {2048, 1024, 512, 256};
__device__ __constant__ int c_S[4]     = {0, 2048, 3072, 3584};
__device__ __constant__ float c_invT[4] = {1.f/2048.f, 1.f/1024.f, 1.f/512.f, 1.f/256.f};

// ---------------- scratch (static device allocations only) ----------------
__device__ float g_value[NROWS_VAL * Cc];   // 31.5 MB
__device__ float g_offattn[NQ * Cc];        // 16.8 MB  (cols 0-127 off, 128-255 attn logits)
__device__ float g_tmp[NQ * Cc];            // 16.8 MB
__device__ float g_loc_scratch[NQ * Mh * Ll * Pp];   // fallback if harness out lacks loc/attn
__device__ float g_attn_scratch[NQ * Mh * Ll * Pp];

// ---------------- f32x2 helpers ----------------
__device__ __forceinline__ unsigned long long pack2(float lo, float hi) {
    unsigned long long r;
    asm("mov.b64 %0, {%1, %2};" : "=l"(r) : "r"(__float_as_uint(lo)), "r"(__float_as_uint(hi)));
    return r;
}
__device__ __forceinline__ unsigned long long fma2(unsigned long long a, unsigned long long b,
                                                   unsigned long long c) {
    unsigned long long d;
    asm("fma.rn.f32x2 %0, %1, %2, %3;" : "=l"(d) : "l"(a), "l"(b), "l"(c));
    return d;
}
__device__ __forceinline__ void unpack2(unsigned long long v, float& lo, float& hi) {
    unsigned int a, b;
    asm("mov.b64 {%0, %1}, %2;" : "=r"(a), "=r"(b) : "l"(v));
    lo = __uint_as_float(a);
    hi = __uint_as_float(b);
}

// ---------------- GEMM: C[M x Nn] = A[M x 256] @ B[256 x Nn] + bias ----------------
// BM=128 BN=128 BK=16, 256 threads, 8x8 per thread via f32x2 (8x4 pairs).
// A tile stored in shared as duplicated pairs (a,a); B tile as natural (b0,b1) pairs.
// Reader B mapping: rB[j] = Bs2[k][16*j + tx]  -> thread covers cols {32j + 2tx, +1}.
__global__ __launch_bounds__(256, 2)
void gemm_bias_kernel(const float* __restrict__ A, const float* __restrict__ B,
                      const float* __restrict__ bias, float* __restrict__ C,
                      int Nn, int ldc, int coff)
{
    __shared__ unsigned long long As2[16][128];  // 16 KB (dup pairs, indexed [k][m])
    __shared__ unsigned long long Bs2[16][64];   // 8 KB  (pairs, indexed [k][n/2])

    const int tid = threadIdx.x;
    const int tx = tid & 15;     // n-group
    const int ty = tid >> 4;     // m-group
    const int m0 = blockIdx.y * 128;
    const int n0 = blockIdx.x * 128;

    // loader mapping
    const int ar = tid >> 1;           // A row 0..127
    const int ak = (tid & 1) * 8;      // A k offset 0/8
    const int bk = tid >> 4;           // B k row 0..15
    const int bn = (tid & 15) * 8;     // B n offset (floats)

    const float* Aptr = A + (size_t)(m0 + ar) * 256 + ak;
    const float* Bptr = B + (size_t)bk * Nn + n0 + bn;

    float4 pa0 = *(const float4*)(Aptr);
    float4 pa1 = *(const float4*)(Aptr + 4);
    float4 pb0 = *(const float4*)(Bptr);
    float4 pb1 = *(const float4*)(Bptr + 4);

    unsigned long long acc[8][4];
#pragma unroll
    for (int i = 0; i < 8; i++)
#pragma unroll
        for (int j = 0; j < 4; j++) acc[i][j] = 0ull;

    for (int kt = 0; kt < 16; ++kt) {
        // stage prefetched tile into shared
        As2[ak + 0][ar] = pack2(pa0.x, pa0.x);
        As2[ak + 1][ar] = pack2(pa0.y, pa0.y);
        As2[ak + 2][ar] = pack2(pa0.z, pa0.z);
        As2[ak + 3][ar] = pack2(pa0.w, pa0.w);
        As2[ak + 4][ar] = pack2(pa1.x, pa1.x);
        As2[ak + 5][ar] = pack2(pa1.y, pa1.y);
        As2[ak + 6][ar] = pack2(pa1.z, pa1.z);
        As2[ak + 7][ar] = pack2(pa1.w, pa1.w);
        Bs2[bk][(bn >> 1) + 0] = pack2(pb0.x, pb0.y);
        Bs2[bk][(bn >> 1) + 1] = pack2(pb0.z, pb0.w);
        Bs2[bk][(bn >> 1) + 2] = pack2(pb1.x, pb1.y);
        Bs2[bk][(bn >> 1) + 3] = pack2(pb1.z, pb1.w);
        __syncthreads();

        if (kt < 15) {
            const float* ap = Aptr + (kt + 1) * 16;
            const float* bp = Bptr + (size_t)(kt + 1) * 16 * Nn;
            pa0 = *(const float4*)(ap);
            pa1 = *(const float4*)(ap + 4);
            pb0 = *(const float4*)(bp);
            pb1 = *(const float4*)(bp + 4);
        }

#pragma unroll
        for (int k = 0; k < 16; ++k) {
            unsigned long long rA[8], rB[4];
#pragma unroll
            for (int i = 0; i < 8; i++) rA[i] = As2[k][ty * 8 + i];
#pragma unroll
            for (int j = 0; j < 4; j++) rB[j] = Bs2[k][j * 16 + tx];
#pragma unroll
            for (int i = 0; i < 8; i++)
#pragma unroll
                for (int j = 0; j < 4; j++) acc[i][j] = fma2(rA[i], rB[j], acc[i][j]);
        }
        __syncthreads();
    }

    // epilogue: acc[i][j] -> rows m0+ty*8+i, cols n0 + 32j + 2tx (+1)
    float blo[4], bhi[4];
#pragma unroll
    for (int j = 0; j < 4; j++) {
        int c = n0 + 32 * j + 2 * tx;
        blo[j] = bias[c];
        bhi[j] = bias[c + 1];
    }
#pragma unroll
    for (int i = 0; i < 8; i++) {
        float* crow = C + (size_t)(m0 + ty * 8 + i) * ldc + coff + n0;
#pragma unroll
        for (int j = 0; j < 4; j++) {
            float lo, hi;
            unpack2(acc[i][j], lo, hi);
            float2 v = make_float2(lo + blo[j], hi + bhi[j]);
            *(float2*)(crow + 32 * j + 2 * tx) = v;
        }
    }
}

// ---------------- loc + softmax(attn) ----------------
// one thread per (n,q,m); reads raw off/attn logits, writes loc and softmaxed attn
__global__ void locattn_kernel(const float* __restrict__ offattn,
                               const float* __restrict__ refp,
                               float* __restrict__ loc_out,
                               float* __restrict__ attn_out)
{
    int idx = blockIdx.x * blockDim.x + threadIdx.x;   // 0..131071
    if (idx >= NQ * Mh) return;
    int m = idx & 7;
    int nq = idx >> 3;

    const float* off  = offattn + (size_t)nq * 256 + m * 16;
    const float* alog = off + 128;

    float a[16];
    float mx = -1e30f;
#pragma unroll
    for (int j = 0; j < 16; j++) { a[j] = alog[j]; mx = fmaxf(mx, a[j]); }
    float s = 0.f;
#pragma unroll
    for (int j = 0; j < 16; j++) { a[j] = expf(a[j] - mx); s += a[j]; }
    float inv = 1.f / s;

    float rp[4];
#pragma unroll
    for (int l = 0; l < 4; l++) rp[l] = refp[(size_t)nq * 4 + l];

    size_t ob = (size_t)idx * 16;
#pragma unroll
    for (int j = 0; j < 16; j++) {
        int l = j >> 2;
        loc_out[ob + j]  = rp[l] + off[j] * c_invT[l];
        attn_out[ob + j] = a[j] * inv;
    }
}

// ---------------- bilinear temporal sampling + attention-weighted sum ----------------
// one warp per (n,q,m); lane = channel d
__global__ void sample_kernel(const float* __restrict__ value,
                              const float* __restrict__ loc,
                              const float* __restrict__ attn,
                              float* __restrict__ outv)
{
    int warp = (blockIdx.x * blockDim.x + threadIdx.x) >> 5;
    int lane = threadIdx.x & 31;
    if (warp >= NQ * Mh) return;
    int m  = warp & 7;
    int nq = warp >> 3;
    int n  = nq >> 11;                 // LQ = 2048

    // lanes 0-15 hold attn weights, lanes 16-31 hold loc values
    size_t b16 = (size_t)warp * 16;
    float myv = (lane < 16) ? attn[b16 + lane] : loc[b16 + lane - 16];

    float acc = 0.f;
    const float* vbase = value + (size_t)n * Ssum * 256 + m * 32 + lane;

#pragma unroll
    for (int lp = 0; lp < 16; ++lp) {
        float w  = __shfl_sync(0xffffffffu, myv, lp);
        float lv = __shfl_sync(0xffffffffu, myv, 16 + lp);
        int l = lp >> 2;
        int T = c_T[l];
        float pos  = lv * (float)T - 0.5f;
        float x0f  = floorf(pos);
        float frac = pos - x0f;
        int x0 = (int)x0f;
        float w0 = (x0 >= 0 && x0 < T) ? (1.f - frac) : 0.f;
        float w1 = (x0 + 1 >= 0 && x0 + 1 < T) ? frac : 0.f;
        if (w0 != 0.f || w1 != 0.f) {          // warp-uniform branch
            int i0 = min(max(x0, 0), T - 1);
            int i1 = min(max(x0 + 1, 0), T - 1);
            const float* p = vbase + (size_t)c_S[l] * 256;
            float v0 = p[(size_t)i0 * 256];
            float v1 = p[(size_t)i1 * 256];
            acc += w * (w0 * v0 + w1 * v1);
        }
    }
    outv[(size_t)warp * 32 + lane] = acc;      // (N, LQ, M*DH) == (N, LQ, C)
}

// ---------------- launch ----------------
extern "C" void kernel_launch(void* const* d_in, const int* in_sizes, int n_in,
                              void* d_out, int out_size)
{
    const float* query         = (const float*)d_in[0];
    const float* refpts        = (const float*)d_in[1];
    const float* input_flatten = (const float*)d_in[2];
    // d_in[3] = temporal_lens, d_in[4] = level_start_index: static, hardcoded (dtype-ambiguous)
    const float* W_off  = (const float*)d_in[5];
    const float* b_off  = (const float*)d_in[6];
    const float* W_attn = (const float*)d_in[7];
    const float* b_attn = (const float*)d_in[8];
    const float* W_val  = (const float*)d_in[9];
    const float* b_val  = (const float*)d_in[10];
    const float* W_out  = (const float*)d_in[11];
    const float* b_out  = (const float*)d_in[12];
    float* out = (float*)d_out;

    float *gv, *goa, *gt, *gls, *gas;
    cudaGetSymbolAddress((void**)&gv,  g_value);
    cudaGetSymbolAddress((void**)&goa, g_offattn);
    cudaGetSymbolAddress((void**)&gt,  g_tmp);
    cudaGetSymbolAddress((void**)&gls, g_loc_scratch);
    cudaGetSymbolAddress((void**)&gas, g_attn_scratch);

    const int OUT_ELEMS  = Nb * LQ * Cc;            // 4194304
    const int LOCA_ELEMS = NQ * Mh * 16;            // 2097152
    float* loc_out  = (out_size >= OUT_ELEMS + 2 * LOCA_ELEMS) ? out + OUT_ELEMS : gls;
    float* attn_out = (out_size >= OUT_ELEMS + 2 * LOCA_ELEMS) ? out + OUT_ELEMS + LOCA_ELEMS : gas;

    // 1. value projection: (30720 x 256) @ (256 x 256)
    gemm_bias_kernel<<<dim3(2, NROWS_VAL / 128), 256>>>(input_flatten, W_val, b_val, gv, 256, 256, 0);
    // 2. offsets + attention logits: (16384 x 256) @ (256 x 128) x2
    gemm_bias_kernel<<<dim3(1, NQ / 128), 256>>>(query, W_off,  b_off,  goa, 128, 256, 0);
    gemm_bias_kernel<<<dim3(1, NQ / 128), 256>>>(query, W_attn, b_attn, goa, 128, 256, 128);
    // 3. sampling locations + softmax weights (also kernel outputs 2 & 3)
    locattn_kernel<<<(NQ * Mh) / 256, 256>>>(goa, refpts, loc_out, attn_out);
    // 4. deformable sampling
    sample_kernel<<<(NQ * Mh) / 8, 256>>>(gv, loc_out, attn_out, gt);
    // 5. output projection -> d_out[0 : 4194304]
    gemm_bias_kernel<<<dim3(2, NQ / 128), 256>>>(gt, W_out, b_out, out, 256, 256, 0);
}

// round 6
// speedup vs baseline: 1.5953x; 1.5953x over previous
#include <cuda_runtime.h>
#include <cuda_fp16.h>
#include <cstdint>

// ---------------- problem constants ----------------
#define Nb   8
#define LQ   2048
#define Cc   256
#define NQ   (Nb*LQ)        // 16384
#define Ssum 3840
#define NROWS_VAL (Nb*Ssum) // 30720

__device__ __constant__ int   c_T[4]    = {2048, 1024, 512, 256};
__device__ __constant__ int   c_S[4]    = {0, 2048, 3072, 3584};
__device__ __constant__ float c_invT[4] = {1.f/2048.f, 1.f/1024.f, 1.f/512.f, 1.f/256.f};

// ---------------- static scratch ----------------
__device__ float  g_value[NROWS_VAL * Cc];      // fp32 value projection (31.5 MB)
__device__ float  g_offattn[NQ * Cc];           // off logits (cols 0-127) + attn logits (128-255)
__device__ __half g_ah[NROWS_VAL * Cc];         // activation hi (reused across phases)
__device__ __half g_al[NROWS_VAL * Cc];         // activation lo
__device__ __half g_wh[4][Cc * Cc];             // transposed weights hi: 0=val 1=off||attn(2 halves) 3=out
__device__ __half g_wl[4][Cc * Cc];
__device__ float  g_loc_s[NQ * 8 * 16];
__device__ float  g_attn_s[NQ * 8 * 16];

// ---------------- helpers ----------------
__device__ __forceinline__ uint32_t smem_u32(const void* p) {
    uint32_t a;
    asm("{ .reg .u64 t; cvta.to.shared.u64 t, %1; cvt.u32.u64 %0, t; }" : "=r"(a) : "l"(p));
    return a;
}
__device__ __forceinline__ void ldmatrix_x4(uint32_t& r0, uint32_t& r1, uint32_t& r2, uint32_t& r3,
                                            uint32_t addr) {
    asm volatile("ldmatrix.sync.aligned.m8n8.x4.shared.b16 {%0,%1,%2,%3}, [%4];"
                 : "=r"(r0), "=r"(r1), "=r"(r2), "=r"(r3) : "r"(addr));
}
__device__ __forceinline__ void mma16816(float* c, uint32_t a0, uint32_t a1, uint32_t a2, uint32_t a3,
                                         uint32_t b0, uint32_t b1) {
    asm volatile("mma.sync.aligned.m16n8k16.row.col.f32.f16.f16.f32 "
                 "{%0,%1,%2,%3},{%4,%5,%6,%7},{%8,%9},{%0,%1,%2,%3};"
                 : "+f"(c[0]), "+f"(c[1]), "+f"(c[2]), "+f"(c[3])
                 : "r"(a0), "r"(a1), "r"(a2), "r"(a3), "r"(b0), "r"(b1));
}

// ---------------- HMMA GEMM: C[M x Nn] = A[M,256] @ Bt[Nn,256]^T + bias ----------------
// A, Bt are fp16 hi/lo split; 3-term compensated product (hh + hl + lh), fp32 accum.
// Block 128x128, 8 warps (4m x 2n), warp tile 32x64. K in 2 chunks of 128.
// smem per chunk: Ah/Al/Bh/Bl tiles of [128][128] fp16 (32 KB each) = 128 KB.
#define TILE_B 32768
#define SWZA(r, k) ((r) * 256 + (((((k) >> 3) ^ ((r) & 7))) << 4))   // byte addr inside a tile

__global__ __launch_bounds__(256, 1)
void hgemm_kernel(const __half* __restrict__ Ah, const __half* __restrict__ Al,
                  const __half* __restrict__ Bh, const __half* __restrict__ Bl,
                  const float* __restrict__ bias0, const float* __restrict__ bias1,
                  int bsplit, float* __restrict__ C)
{
    extern __shared__ char smem[];
    const uint32_t sb = smem_u32(smem);
    const int tid = threadIdx.x;
    const int wid = tid >> 5;
    const int lane = tid & 31;
    const int m0 = blockIdx.x * 128;
    const int n0 = blockIdx.y * 128;
    const int wm = (wid & 3) * 32;   // warp row base within block
    const int wn = (wid >> 2) * 64;  // warp col base within block

    float acc[2][8][4];
#pragma unroll
    for (int i = 0; i < 2; i++)
#pragma unroll
        for (int j = 0; j < 8; j++)
#pragma unroll
            for (int k = 0; k < 4; k++) acc[i][j][k] = 0.f;

    // precomputed ldmatrix lane addresses (byte offsets inside a tile)
    const int a_r  = (lane & 15);                 // + wm + mi*16
    const int a_k8 = (lane >> 4) << 3;            // + k0
    const int b_r  = (lane & 7) + ((lane >> 4) << 3);  // + wn + np*16
    const int b_k8 = ((lane >> 3) & 1) << 3;      // + k0

    for (int kc = 0; kc < 2; ++kc) {
        // ---- load 4 tiles: rows r (128), k chunk kc*128 .. +128 ----
#pragma unroll
        for (int i = 0; i < 8; i++) {
            int lin = i * 256 + tid;
            int r = lin >> 4, c = lin & 15;               // c = 16B chunk (8 halfs)
            size_t gA = (size_t)(m0 + r) * 256 + kc * 128 + c * 8;
            size_t gB = (size_t)(n0 + r) * 256 + kc * 128 + c * 8;
            uint32_t sw = (uint32_t)(r * 256 + ((c ^ (r & 7)) << 4));
            *(uint4*)(smem + 0 * TILE_B + sw) = *(const uint4*)(Ah + gA);
            *(uint4*)(smem + 1 * TILE_B + sw) = *(const uint4*)(Al + gA);
            *(uint4*)(smem + 2 * TILE_B + sw) = *(const uint4*)(Bh + gB);
            *(uint4*)(smem + 3 * TILE_B + sw) = *(const uint4*)(Bl + gB);
        }
        __syncthreads();

#pragma unroll
        for (int pass = 0; pass < 3; ++pass) {
            const uint32_t Abase = sb + (pass == 2 ? 1 : 0) * TILE_B;   // hh,hl use Ah; lh uses Al
            const uint32_t Bbase = sb + (pass == 1 ? 3 : 2) * TILE_B;   // hh,lh use Bh; hl uses Bl
#pragma unroll
            for (int ks = 0; ks < 8; ++ks) {
                const int k0 = ks * 16;
                uint32_t a[2][4], b[4][4];
#pragma unroll
                for (int mi = 0; mi < 2; mi++) {
                    int r = wm + mi * 16 + a_r;
                    int kk = k0 + a_k8;
                    ldmatrix_x4(a[mi][0], a[mi][1], a[mi][2], a[mi][3], Abase + SWZA(r, kk));
                }
#pragma unroll
                for (int np = 0; np < 4; np++) {
                    int r = wn + np * 16 + b_r;
                    int kk = k0 + b_k8;
                    ldmatrix_x4(b[np][0], b[np][1], b[np][2], b[np][3], Bbase + SWZA(r, kk));
                }
#pragma unroll
                for (int mi = 0; mi < 2; mi++)
#pragma unroll
                    for (int ni = 0; ni < 8; ni++)
                        mma16816(acc[mi][ni], a[mi][0], a[mi][1], a[mi][2], a[mi][3],
                                 b[ni >> 1][(ni & 1) * 2], b[ni >> 1][(ni & 1) * 2 + 1]);
            }
        }
        __syncthreads();
    }

    // ---- epilogue ----
    const int g  = lane >> 2;
    const int tq = lane & 3;
#pragma unroll
    for (int ni = 0; ni < 8; ni++) {
        int c = n0 + wn + ni * 8 + 2 * tq;
        float bv0 = (c     < bsplit) ? bias0[c]     : bias1[c - bsplit];
        float bv1 = (c + 1 < bsplit) ? bias0[c + 1] : bias1[c + 1 - bsplit];
#pragma unroll
        for (int mi = 0; mi < 2; mi++) {
            int row = m0 + wm + mi * 16 + g;
            *(float2*)(C + (size_t)row * 256 + c)       = make_float2(acc[mi][ni][0] + bv0,
                                                                      acc[mi][ni][1] + bv1);
            *(float2*)(C + (size_t)(row + 8) * 256 + c) = make_float2(acc[mi][ni][2] + bv0,
                                                                      acc[mi][ni][3] + bv1);
        }
    }
}

// ---------------- fp32 -> fp16 hi/lo split (activations) ----------------
__global__ void split_kernel(const float* __restrict__ src, __half* __restrict__ hi,
                             __half* __restrict__ lo, int n4)
{
    int i = blockIdx.x * blockDim.x + threadIdx.x;
    if (i >= n4) return;
    float4 v = ((const float4*)src)[i];
    __half h0 = __float2half(v.x), h1 = __float2half(v.y);
    __half h2 = __float2half(v.z), h3 = __float2half(v.w);
    __half l0 = __float2half(v.x - __half2float(h0));
    __half l1 = __float2half(v.y - __half2float(h1));
    __half l2 = __float2half(v.z - __half2float(h2));
    __half l3 = __float2half(v.w - __half2float(h3));
    ((__half2*)hi)[2 * i]     = __halves2half2(h0, h1);
    ((__half2*)hi)[2 * i + 1] = __halves2half2(h2, h3);
    ((__half2*)lo)[2 * i]     = __halves2half2(l0, l1);
    ((__half2*)lo)[2 * i + 1] = __halves2half2(l2, l3);
}

// ---------------- weight transpose + split: W[256,Nn] -> Wt[Nn,256] fp16 hi/lo ----------------
__global__ void tsplit_w_kernel(const float* __restrict__ W, __half* __restrict__ hi,
                                __half* __restrict__ lo, int Nn)
{
    int i = blockIdx.x * blockDim.x + threadIdx.x;
    if (i >= 256 * Nn) return;
    int n = i >> 8, k = i & 255;
    float x = W[(size_t)k * Nn + n];
    __half h = __float2half(x);
    hi[i] = h;
    lo[i] = __float2half(x - __half2float(h));
}

// ---------------- fused loc/softmax + bilinear sampling ----------------
// one warp per (nq, m). lanes 0-15: loc; lanes 16-31: softmaxed attn.
__global__ void sample_kernel(const float* __restrict__ value,
                              const float* __restrict__ goa,
                              const float* __restrict__ refp,
                              float* __restrict__ loc_out,
                              float* __restrict__ attn_out,
                              __half* __restrict__ out_h,
                              __half* __restrict__ out_l)
{
    int warp = (blockIdx.x * blockDim.x + threadIdx.x) >> 5;
    int lane = threadIdx.x & 31;
    if (warp >= NQ * 8) return;
    int m  = warp & 7;
    int nq = warp >> 3;
    int n  = nq >> 11;
    int j  = lane & 15;

    float v = goa[(size_t)nq * 256 + (lane < 16 ? m * 16 + j : 128 + m * 16 + j)];

    // softmax within each 16-lane half (lower half result is garbage, unused)
    float mx = v;
#pragma unroll
    for (int o = 1; o < 16; o <<= 1) mx = fmaxf(mx, __shfl_xor_sync(0xffffffffu, mx, o));
    float e = __expf(v - mx);
    float s = e;
#pragma unroll
    for (int o = 1; o < 16; o <<= 1) s += __shfl_xor_sync(0xffffffffu, s, o);

    int l4 = j >> 2;
    float myv = (lane < 16) ? (refp[(size_t)nq * 4 + l4] + v * c_invT[l4]) : (e / s);

    if (lane < 16) loc_out[(size_t)warp * 16 + j]  = myv;
    else           attn_out[(size_t)warp * 16 + j] = myv;

    float acc = 0.f;
    const float* vbase = value + (size_t)n * Ssum * 256 + m * 32 + lane;

#pragma unroll
    for (int lp = 0; lp < 16; ++lp) {
        float lv = __shfl_sync(0xffffffffu, myv, lp);        // loc
        float w  = __shfl_sync(0xffffffffu, myv, 16 + lp);   // attn weight
        int l = lp >> 2;
        int T = c_T[l];
        float pos  = lv * (float)T - 0.5f;
        float x0f  = floorf(pos);
        float frac = pos - x0f;
        int x0 = (int)x0f;
        float w0 = (x0 >= 0 && x0 < T) ? (1.f - frac) : 0.f;
        float w1 = (x0 + 1 >= 0 && x0 + 1 < T) ? frac : 0.f;
        if (w0 != 0.f || w1 != 0.f) {
            int i0 = min(max(x0, 0), T - 1);
            int i1 = min(max(x0 + 1, 0), T - 1);
            const float* p = vbase + (size_t)c_S[l] * 256;
            float v0 = p[(size_t)i0 * 256];
            float v1 = p[(size_t)i1 * 256];
            acc += w * (w0 * v0 + w1 * v1);
        }
    }
    __half h = __float2half(acc);
    out_h[(size_t)warp * 32 + lane] = h;
    out_l[(size_t)warp * 32 + lane] = __float2half(acc - __half2float(h));
}

// ---------------- launch ----------------
extern "C" void kernel_launch(void* const* d_in, const int* in_sizes, int n_in,
                              void* d_out, int out_size)
{
    const float* query         = (const float*)d_in[0];
    const float* refpts        = (const float*)d_in[1];
    const float* input_flatten = (const float*)d_in[2];
    const float* W_off  = (const float*)d_in[5];
    const float* b_off  = (const float*)d_in[6];
    const float* W_attn = (const float*)d_in[7];
    const float* b_attn = (const float*)d_in[8];
    const float* W_val  = (const float*)d_in[9];
    const float* b_val  = (const float*)d_in[10];
    const float* W_out  = (const float*)d_in[11];
    const float* b_out  = (const float*)d_in[12];
    float* out = (float*)d_out;

    float *gv, *goa, *gls, *gas;
    __half *gah, *gal, *gwh, *gwl;
    cudaGetSymbolAddress((void**)&gv,  g_value);
    cudaGetSymbolAddress((void**)&goa, g_offattn);
    cudaGetSymbolAddress((void**)&gah, g_ah);
    cudaGetSymbolAddress((void**)&gal, g_al);
    cudaGetSymbolAddress((void**)&gwh, g_wh);
    cudaGetSymbolAddress((void**)&gwl, g_wl);
    cudaGetSymbolAddress((void**)&gls, g_loc_s);
    cudaGetSymbolAddress((void**)&gas, g_attn_s);

    const int OUT_ELEMS  = NQ * Cc;       // 4194304
    const int LOCA_ELEMS = NQ * 8 * 16;   // 2097152
    float* loc_out  = (out_size >= OUT_ELEMS + 2 * LOCA_ELEMS) ? out + OUT_ELEMS : gls;
    float* attn_out = (out_size >= OUT_ELEMS + 2 * LOCA_ELEMS) ? out + OUT_ELEMS + LOCA_ELEMS : gas;

    const int SMEM = 4 * TILE_B;  // 128 KB
    cudaFuncSetAttribute(hgemm_kernel, cudaFuncAttributeMaxDynamicSharedMemorySize, SMEM);

    __half* wvh = gwh;               __half* wvl = gwl;                // W_val^T   [256][256]
    __half* wqh = gwh + 1 * Cc * Cc; __half* wql = gwl + 1 * Cc * Cc;  // [W_off;W_attn]^T [256][256]
    __half* woh = gwh + 3 * Cc * Cc; __half* wol = gwl + 3 * Cc * Cc;  // W_out^T   [256][256]

    // weight transpose + split (tiny)
    tsplit_w_kernel<<<(256 * 256) / 256, 256>>>(W_val,  wvh, wvl, 256);
    tsplit_w_kernel<<<(256 * 128) / 256, 256>>>(W_off,  wqh, wql, 128);
    tsplit_w_kernel<<<(256 * 128) / 256, 256>>>(W_attn, wqh + 128 * 256, wql + 128 * 256, 128);
    tsplit_w_kernel<<<(256 * 256) / 256, 256>>>(W_out,  woh, wol, 256);

    // 1. value projection: (30720 x 256) @ (256 x 256)
    split_kernel<<<(NROWS_VAL * 64) / 256, 256>>>(input_flatten, gah, gal, NROWS_VAL * 64);
    hgemm_kernel<<<dim3(NROWS_VAL / 128, 2), 256, SMEM>>>(gah, gal, wvh, wvl, b_val, b_val, 512, gv);

    // 2. fused offsets + attention logits: (16384 x 256) @ (256 x 256)
    split_kernel<<<(NQ * 64) / 256, 256>>>(query, gah, gal, NQ * 64);
    hgemm_kernel<<<dim3(NQ / 128, 2), 256, SMEM>>>(gah, gal, wqh, wql, b_off, b_attn, 128, goa);

    // 3. fused loc/softmax + deformable sampling -> fp16 hi/lo (feeds out-proj)
    sample_kernel<<<(NQ * 8) / 8, 256>>>(gv, goa, refpts, loc_out, attn_out, gah, gal);

    // 4. output projection -> d_out
    hgemm_kernel<<<dim3(NQ / 128, 2), 256, SMEM>>>(gah, gal, woh, wol, b_out, b_out, 512, out);
}

// round 7
// speedup vs baseline: 1.8299x; 1.1471x over previous
#include <cuda_runtime.h>
#include <cuda_fp16.h>
#include <cstdint>

// ---------------- problem constants ----------------
#define Nb   8
#define LQ   2048
#define Cc   256
#define NQ   (Nb*LQ)        // 16384
#define Ssum 3840
#define NROWS_VAL (Nb*Ssum) // 30720

__device__ __constant__ int   c_T[4]    = {2048, 1024, 512, 256};
__device__ __constant__ int   c_S[4]    = {0, 2048, 3072, 3584};
__device__ __constant__ float c_invT[4] = {1.f/2048.f, 1.f/1024.f, 1.f/512.f, 1.f/256.f};

// ---------------- static scratch ----------------
__device__ float  g_value[NROWS_VAL * Cc];      // fp32 value projection (31.5 MB)
__device__ float  g_offattn[NQ * Cc];           // off logits (0-127) + attn logits (128-255)
__device__ float  g_tmp[NQ * Cc];               // sampled tensor (feeds out-proj)
__device__ __half g_wh[4][Cc * Cc];             // transposed weight hi: 0=val, 1,2=off||attn, 3=out
__device__ __half g_wl[4][Cc * Cc];
__device__ float  g_loc_s[NQ * 8 * 16];
__device__ float  g_attn_s[NQ * 8 * 16];

// ---------------- helpers ----------------
__device__ __forceinline__ uint32_t smem_u32(const void* p) {
    uint32_t a;
    asm("{ .reg .u64 t; cvta.to.shared.u64 t, %1; cvt.u32.u64 %0, t; }" : "=r"(a) : "l"(p));
    return a;
}
__device__ __forceinline__ void ldmatrix_x4(uint32_t& r0, uint32_t& r1, uint32_t& r2, uint32_t& r3,
                                            uint32_t addr) {
    asm volatile("ldmatrix.sync.aligned.m8n8.x4.shared.b16 {%0,%1,%2,%3}, [%4];"
                 : "=r"(r0), "=r"(r1), "=r"(r2), "=r"(r3) : "r"(addr));
}
__device__ __forceinline__ void mma16816(float* c, uint32_t a0, uint32_t a1, uint32_t a2, uint32_t a3,
                                         uint32_t b0, uint32_t b1) {
    asm volatile("mma.sync.aligned.m16n8k16.row.col.f32.f16.f16.f32 "
                 "{%0,%1,%2,%3},{%4,%5,%6,%7},{%8,%9},{%0,%1,%2,%3};"
                 : "+f"(c[0]), "+f"(c[1]), "+f"(c[2]), "+f"(c[3])
                 : "r"(a0), "r"(a1), "r"(a2), "r"(a3), "r"(b0), "r"(b1));
}
__device__ __forceinline__ void cp_async16(uint32_t dst, const void* src) {
    asm volatile("cp.async.cg.shared.global [%0], [%1], 16;" :: "r"(dst), "l"(src));
}
__device__ __forceinline__ void cp_async_wait_all() {
    asm volatile("cp.async.commit_group;\n\tcp.async.wait_group 0;" ::: "memory");
}

// ---------------- HMMA GEMM with fused fp32->fp16 hi/lo split of A ----------------
// C[M x 256] = A[M,256] @ Bt[256,256]^T + bias.  3-term compensated (hh + hl + lh), fp32 acc.
// Block 128x128, 8 warps (4m x 2n), warp tile 32x64, K in 2 chunks of 128.
// Dual dispatch: blocks [0,nx0) run problem 0, blocks [nx0,gridDim.x) run problem 1.
#define TILE_B 32768
#define SWZA(r, k) ((r) * 256 + (((((k) >> 3) ^ ((r) & 7))) << 4))

__global__ __launch_bounds__(256, 1)
void hgemm_kernel(const float* __restrict__ A0, const __half* __restrict__ B0h,
                  const __half* __restrict__ B0l, const float* __restrict__ b0a,
                  const float* __restrict__ b0b, int bsplit0, float* __restrict__ C0, int nx0,
                  const float* __restrict__ A1, const __half* __restrict__ B1h,
                  const __half* __restrict__ B1l, const float* __restrict__ b1a,
                  const float* __restrict__ b1b, int bsplit1, float* __restrict__ C1)
{
    extern __shared__ char smem[];
    const uint32_t sb = smem_u32(smem);
    const int tid = threadIdx.x;
    const int wid = tid >> 5;
    const int lane = tid & 31;

    const bool p0 = ((int)blockIdx.x < nx0);
    const float*  A     = p0 ? A0 : A1;
    const __half* Bh    = p0 ? B0h : B1h;
    const __half* Bl    = p0 ? B0l : B1l;
    const float*  bias0 = p0 ? b0a : b1a;
    const float*  bias1 = p0 ? b0b : b1b;
    const int     bsplit = p0 ? bsplit0 : bsplit1;
    float*        C     = p0 ? C0 : C1;
    const int m0 = (p0 ? blockIdx.x : blockIdx.x - nx0) * 128;
    const int n0 = blockIdx.y * 128;
    const int wm = (wid & 3) * 32;
    const int wn = (wid >> 2) * 64;

    float acc[2][8][4];
#pragma unroll
    for (int i = 0; i < 2; i++)
#pragma unroll
        for (int j = 0; j < 8; j++)
#pragma unroll
            for (int k = 0; k < 4; k++) acc[i][j][k] = 0.f;

    const int a_r  = (lane & 15);
    const int a_k8 = (lane >> 4) << 3;
    const int b_r  = (lane & 7) + ((lane >> 4) << 3);
    const int b_k8 = ((lane >> 3) & 1) << 3;

    for (int kc = 0; kc < 2; ++kc) {
        // B tiles via cp.async (overlaps with A convert below)
#pragma unroll
        for (int i = 0; i < 8; i++) {
            int lin = i * 256 + tid;
            int r = lin >> 4, c = lin & 15;
            size_t gB = (size_t)(n0 + r) * 256 + kc * 128 + c * 8;
            uint32_t sw = (uint32_t)(r * 256 + ((c ^ (r & 7)) << 4));
            cp_async16(sb + 2 * TILE_B + sw, Bh + gB);
            cp_async16(sb + 3 * TILE_B + sw, Bl + gB);
        }
        // A tiles: load fp32, split to hi/lo fp16, store swizzled
#pragma unroll
        for (int i = 0; i < 8; i++) {
            int lin = i * 256 + tid;
            int r = lin >> 4, c = lin & 15;
            const float* ga = A + (size_t)(m0 + r) * 256 + kc * 128 + c * 8;
            float4 v0 = *(const float4*)ga;
            float4 v1 = *(const float4*)(ga + 4);
            __half h[8], l[8];
            float f[8] = {v0.x, v0.y, v0.z, v0.w, v1.x, v1.y, v1.z, v1.w};
#pragma unroll
            for (int e = 0; e < 8; e++) {
                h[e] = __float2half_rn(f[e]);
                l[e] = __float2half_rn(f[e] - __half2float(h[e]));
            }
            uint32_t sw = (uint32_t)(r * 256 + ((c ^ (r & 7)) << 4));
            *(uint4*)(smem + 0 * TILE_B + sw) = *(uint4*)h;
            *(uint4*)(smem + 1 * TILE_B + sw) = *(uint4*)l;
        }
        cp_async_wait_all();
        __syncthreads();

#pragma unroll
        for (int pass = 0; pass < 3; ++pass) {
            const uint32_t Abase = sb + (pass == 2 ? 1 : 0) * TILE_B;
            const uint32_t Bbase = sb + (pass == 1 ? 3 : 2) * TILE_B;
#pragma unroll
            for (int ks = 0; ks < 8; ++ks) {
                const int k0 = ks * 16;
                uint32_t a[2][4], b[4][4];
#pragma unroll
                for (int mi = 0; mi < 2; mi++)
                    ldmatrix_x4(a[mi][0], a[mi][1], a[mi][2], a[mi][3],
                                Abase + SWZA(wm + mi * 16 + a_r, k0 + a_k8));
#pragma unroll
                for (int np = 0; np < 4; np++)
                    ldmatrix_x4(b[np][0], b[np][1], b[np][2], b[np][3],
                                Bbase + SWZA(wn + np * 16 + b_r, k0 + b_k8));
#pragma unroll
                for (int mi = 0; mi < 2; mi++)
#pragma unroll
                    for (int ni = 0; ni < 8; ni++)
                        mma16816(acc[mi][ni], a[mi][0], a[mi][1], a[mi][2], a[mi][3],
                                 b[ni >> 1][(ni & 1) * 2], b[ni >> 1][(ni & 1) * 2 + 1]);
            }
        }
        __syncthreads();
    }

    // epilogue
    const int g  = lane >> 2;
    const int tq = lane & 3;
#pragma unroll
    for (int ni = 0; ni < 8; ni++) {
        int c = n0 + wn + ni * 8 + 2 * tq;
        float bv0 = (c     < bsplit) ? bias0[c]     : bias1[c - bsplit];
        float bv1 = (c + 1 < bsplit) ? bias0[c + 1] : bias1[c + 1 - bsplit];
#pragma unroll
        for (int mi = 0; mi < 2; mi++) {
            int row = m0 + wm + mi * 16 + g;
            *(float2*)(C + (size_t)row * 256 + c)       = make_float2(acc[mi][ni][0] + bv0,
                                                                      acc[mi][ni][1] + bv1);
            *(float2*)(C + (size_t)(row + 8) * 256 + c) = make_float2(acc[mi][ni][2] + bv0,
                                                                      acc[mi][ni][3] + bv1);
        }
    }
}

// ---------------- fused weight prep: transpose + fp16 hi/lo split, all 4 matrices ----------------
__global__ void wprep_kernel(const float* __restrict__ W_val, const float* __restrict__ W_off,
                             const float* __restrict__ W_attn, const float* __restrict__ W_out,
                             __half* __restrict__ gwh, __half* __restrict__ gwl)
{
    int idx = blockIdx.x * blockDim.x + threadIdx.x;   // 0 .. 4*65536-1
    int mat = idx >> 16;
    int i   = idx & 65535;
    int n = i >> 8, k = i & 255;

    float x;
    int dst;
    if (mat == 0) {                 // W_val^T -> slot 0
        x = W_val[(size_t)k * 256 + n];
        dst = i;
    } else if (mat == 1) {          // W_off^T -> slot 1 rows [0,128)
        if (n >= 128) return;
        x = W_off[(size_t)k * 128 + n];
        dst = 65536 + n * 256 + k;
    } else if (mat == 2) {          // W_attn^T -> slot 1 rows [128,256)
        if (n >= 128) return;
        x = W_attn[(size_t)k * 128 + n];
        dst = 65536 + (128 + n) * 256 + k;
    } else {                        // W_out^T -> slot 3
        x = W_out[(size_t)k * 256 + n];
        dst = 3 * 65536 + i;
    }
    __half h = __float2half_rn(x);
    gwh[dst] = h;
    gwl[dst] = __float2half_rn(x - __half2float(h));
}

// ---------------- fused loc/softmax + bilinear sampling ----------------
// one warp per (nq, m). lanes 0-15: loc; lanes 16-31: softmaxed attn.
__global__ void sample_kernel(const float* __restrict__ value,
                              const float* __restrict__ goa,
                              const float* __restrict__ refp,
                              float* __restrict__ loc_out,
                              float* __restrict__ attn_out,
                              float* __restrict__ outv)
{
    int warp = (blockIdx.x * blockDim.x + threadIdx.x) >> 5;
    int lane = threadIdx.x & 31;
    if (warp >= NQ * 8) return;
    int m  = warp & 7;
    int nq = warp >> 3;
    int n  = nq >> 11;
    int j  = lane & 15;

    float v = goa[(size_t)nq * 256 + (lane < 16 ? m * 16 + j : 128 + m * 16 + j)];

    // softmax within the upper 16-lane half (lower-half result unused)
    float mx = v;
#pragma unroll
    for (int o = 1; o < 16; o <<= 1) mx = fmaxf(mx, __shfl_xor_sync(0xffffffffu, mx, o));
    float e = __expf(v - mx);
    float s = e;
#pragma unroll
    for (int o = 1; o < 16; o <<= 1) s += __shfl_xor_sync(0xffffffffu, s, o);

    int l4 = j >> 2;
    float myv = (lane < 16) ? (refp[(size_t)nq * 4 + l4] + v * c_invT[l4]) : (e / s);

    if (lane < 16) loc_out[(size_t)warp * 16 + j]  = myv;
    else           attn_out[(size_t)warp * 16 + j] = myv;

    float acc = 0.f;
    const float* vbase = value + (size_t)n * Ssum * 256 + m * 32 + lane;

#pragma unroll
    for (int lp = 0; lp < 16; ++lp) {
        float lv = __shfl_sync(0xffffffffu, myv, lp);        // loc
        float w  = __shfl_sync(0xffffffffu, myv, 16 + lp);   // attn weight
        int l = lp >> 2;
        int T = c_T[l];
        float pos  = lv * (float)T - 0.5f;
        float x0f  = floorf(pos);
        float frac = pos - x0f;
        int x0 = (int)x0f;
        float w0 = (x0 >= 0 && x0 < T) ? (1.f - frac) : 0.f;
        float w1 = (x0 + 1 >= 0 && x0 + 1 < T) ? frac : 0.f;
        if (w0 != 0.f || w1 != 0.f) {
            int i0 = min(max(x0, 0), T - 1);
            int i1 = min(max(x0 + 1, 0), T - 1);
            const float* p = vbase + (size_t)c_S[l] * 256;
            float v0 = p[(size_t)i0 * 256];
            float v1 = p[(size_t)i1 * 256];
            acc += w * (w0 * v0 + w1 * v1);
        }
    }
    outv[(size_t)warp * 32 + lane] = acc;
}

// ---------------- launch ----------------
extern "C" void kernel_launch(void* const* d_in, const int* in_sizes, int n_in,
                              void* d_out, int out_size)
{
    const float* query         = (const float*)d_in[0];
    const float* refpts        = (const float*)d_in[1];
    const float* input_flatten = (const float*)d_in[2];
    const float* W_off  = (const float*)d_in[5];
    const float* b_off  = (const float*)d_in[6];
    const float* W_attn = (const float*)d_in[7];
    const float* b_attn = (const float*)d_in[8];
    const float* W_val  = (const float*)d_in[9];
    const float* b_val  = (const float*)d_in[10];
    const float* W_out  = (const float*)d_in[11];
    const float* b_out  = (const float*)d_in[12];
    float* out = (float*)d_out;

    float *gv, *goa, *gt, *gls, *gas;
    __half *gwh, *gwl;
    cudaGetSymbolAddress((void**)&gv,  g_value);
    cudaGetSymbolAddress((void**)&goa, g_offattn);
    cudaGetSymbolAddress((void**)&gt,  g_tmp);
    cudaGetSymbolAddress((void**)&gwh, g_wh);
    cudaGetSymbolAddress((void**)&gwl, g_wl);
    cudaGetSymbolAddress((void**)&gls, g_loc_s);
    cudaGetSymbolAddress((void**)&gas, g_attn_s);

    const int OUT_ELEMS  = NQ * Cc;       // 4194304
    const int LOCA_ELEMS = NQ * 8 * 16;   // 2097152
    float* loc_out  = (out_size >= OUT_ELEMS + 2 * LOCA_ELEMS) ? out + OUT_ELEMS : gls;
    float* attn_out = (out_size >= OUT_ELEMS + 2 * LOCA_ELEMS) ? out + OUT_ELEMS + LOCA_ELEMS : gas;

    const int SMEM = 4 * TILE_B;  // 128 KB
    cudaFuncSetAttribute(hgemm_kernel, cudaFuncAttributeMaxDynamicSharedMemorySize, SMEM);

    __half* wvh = gwh;               __half* wvl = gwl;                // W_val^T
    __half* wqh = gwh + 1 * Cc * Cc; __half* wql = gwl + 1 * Cc * Cc;  // [W_off;W_attn]^T
    __half* woh = gwh + 3 * Cc * Cc; __half* wol = gwl + 3 * Cc * Cc;  // W_out^T

    // 1. weight transpose + split (one launch)
    wprep_kernel<<<(4 * 65536) / 256, 256>>>(W_val, W_off, W_attn, W_out, gwh, gwl);

    // 2. fused: value projection (240 blocks) + off/attn projection (128 blocks)
    hgemm_kernel<<<dim3(NROWS_VAL / 128 + NQ / 128, 2), 256, SMEM>>>(
        input_flatten, wvh, wvl, b_val, b_val, 512, gv, NROWS_VAL / 128,
        query,         wqh, wql, b_off, b_attn, 128, goa);

    // 3. fused loc/softmax + deformable sampling -> fp32 tmp (also outputs loc & attn)
    sample_kernel<<<(NQ * 8) / 8, 256>>>(gv, goa, refpts, loc_out, attn_out, gt);

    // 4. output projection -> d_out
    hgemm_kernel<<<dim3(NQ / 128, 2), 256, SMEM>>>(
        gt, woh, wol, b_out, b_out, 512, out, NQ / 128,
        gt, woh, wol, b_out, b_out, 512, out);
}

// round 9
// speedup vs baseline: 1.8589x; 1.0158x over previous
#include <cuda_runtime.h>
#include <cuda_fp16.h>
#include <cstdint>

// ---------------- problem constants ----------------
#define Nb   8
#define LQ   2048
#define Cc   256
#define NQ   (Nb*LQ)        // 16384
#define Ssum 3840
#define NROWS_VAL (Nb*Ssum) // 30720

__device__ __constant__ int   c_T[4]    = {2048, 1024, 512, 256};
__device__ __constant__ int   c_S[4]    = {0, 2048, 3072, 3584};
__device__ __constant__ float c_invT[4] = {1.f/2048.f, 1.f/1024.f, 1.f/512.f, 1.f/256.f};

// ---------------- static scratch ----------------
__device__ float  g_value[NROWS_VAL * Cc];      // fp32 value projection (31.5 MB)
__device__ float  g_offattn[NQ * Cc];           // off logits (0-127) + attn logits (128-255)
__device__ float  g_tmp[NQ * Cc];               // sampled tensor (feeds out-proj)
__device__ __half g_wh[4][Cc * Cc];             // transposed weight hi: 0=val, 1,2=off||attn, 3=out
__device__ __half g_wl[4][Cc * Cc];
__device__ float  g_loc_s[NQ * 8 * 16];
__device__ float  g_attn_s[NQ * 8 * 16];

// ---------------- helpers ----------------
__device__ __forceinline__ uint32_t smem_u32(const void* p) {
    uint32_t a;
    asm("{ .reg .u64 t; cvta.to.shared.u64 t, %1; cvt.u32.u64 %0, t; }" : "=r"(a) : "l"(p));
    return a;
}
__device__ __forceinline__ void ldmatrix_x4(uint32_t& r0, uint32_t& r1, uint32_t& r2, uint32_t& r3,
                                            uint32_t addr) {
    asm volatile("ldmatrix.sync.aligned.m8n8.x4.shared.b16 {%0,%1,%2,%3}, [%4];"
                 : "=r"(r0), "=r"(r1), "=r"(r2), "=r"(r3) : "r"(addr));
}
__device__ __forceinline__ void mma16816(float* c, const uint32_t* a, uint32_t b0, uint32_t b1) {
    asm volatile("mma.sync.aligned.m16n8k16.row.col.f32.f16.f16.f32 "
                 "{%0,%1,%2,%3},{%4,%5,%6,%7},{%8,%9},{%0,%1,%2,%3};"
                 : "+f"(c[0]), "+f"(c[1]), "+f"(c[2]), "+f"(c[3])
                 : "r"(a[0]), "r"(a[1]), "r"(a[2]), "r"(a[3]), "r"(b0), "r"(b1));
}
__device__ __forceinline__ void cp_async16(uint32_t dst, const void* src) {
    asm volatile("cp.async.cg.shared.global [%0], [%1], 16;" :: "r"(dst), "l"(src));
}
__device__ __forceinline__ void cp_async_wait_all() {
    asm volatile("cp.async.commit_group;\n\tcp.async.wait_group 0;" ::: "memory");
}

// B resident tile addressing: 64 rows x 256 halfs (512 B/row); chunk-XOR swizzle (low 3 bits)
#define SWZB(r, k) ((r) * 512 + ((((((k) >> 3) & ~7) | ((((k) >> 3) & 7) ^ ((r) & 7)))) << 4))
// A stage addressing: 128 rows x 64 halfs (128 B/row)
#define SWZA(r, k) ((r) * 128 + ((((((k) >> 3) & 7) ^ ((r) & 7))) << 4))

// smem layout (bytes): Bh [0,32K) | Bl [32K,64K) | A stages: s*32K + 64K (Ah 16K, Al 16K)
#define SM_BL  32768
#define SM_AST 65536

// ---------------- pipelined HMMA GEMM with fused fp32->fp16 hi/lo split of A ----------------
// C[M x 256] = A[M,256] @ Bt[256,256]^T + bias.  3-term compensated (hh + hl + lh), fp32 acc.
// Block 128(m) x 64(n); 8 warps = 4m x 2n, warp tile 32x32. K: 4 pipelined chunks of 64.
// Dual dispatch: blocks [0,nx0) run problem 0, rest run problem 1.
__global__ __launch_bounds__(256, 1)
void hgemm_kernel(const float* __restrict__ A0, const __half* __restrict__ B0h,
                  const __half* __restrict__ B0l, const float* __restrict__ b0a,
                  const float* __restrict__ b0b, int bsplit0, float* __restrict__ C0, int nx0,
                  const float* __restrict__ A1, const __half* __restrict__ B1h,
                  const __half* __restrict__ B1l, const float* __restrict__ b1a,
                  const float* __restrict__ b1b, int bsplit1, float* __restrict__ C1)
{
    extern __shared__ char smem[];
    const uint32_t sb = smem_u32(smem);
    const int tid = threadIdx.x;
    const int wid = tid >> 5;
    const int lane = tid & 31;

    const bool p0 = ((int)blockIdx.x < nx0);
    const float*  A      = p0 ? A0 : A1;
    const __half* Bh     = p0 ? B0h : B1h;
    const __half* Bl     = p0 ? B0l : B1l;
    const float*  bias0  = p0 ? b0a : b1a;
    const float*  bias1  = p0 ? b0b : b1b;
    const int     bsplit = p0 ? bsplit0 : bsplit1;
    float*        C      = p0 ? C0 : C1;
    const int m0 = (p0 ? blockIdx.x : blockIdx.x - nx0) * 128;
    const int n0 = blockIdx.y * 64;
    const int wm = (wid & 3) * 32;
    const int wn = (wid >> 2) * 32;

    // ---- B resident load (once): 64 rows x 256 k, hi+lo, via cp.async ----
#pragma unroll
    for (int i = 0; i < 8; i++) {
        int lin = i * 256 + tid;                 // 0..2047
        int r = lin >> 5, c = lin & 31;          // row, 16B-chunk
        size_t g = (size_t)(n0 + r) * 256 + c * 8;
        uint32_t sw = SWZB(r, c * 8);
        cp_async16(sb + sw,          Bh + g);
        cp_async16(sb + SM_BL + sw,  Bl + g);
    }

    // ---- A chunk 0: LDG ----
    const int a_row = tid >> 3;                  // 0..31 group base (x4 iters => 128 rows)
    const int a_c8  = tid & 7;                   // 8-half chunk
    float4 pre[4][2];
#pragma unroll
    for (int i = 0; i < 4; i++) {
        int r = i * 32 + a_row;
        const float* ga = A + (size_t)(m0 + r) * 256 + a_c8 * 8;
        pre[i][0] = *(const float4*)(ga);
        pre[i][1] = *(const float4*)(ga + 4);
    }
    // convert chunk 0 -> stage 0
#pragma unroll
    for (int i = 0; i < 4; i++) {
        int r = i * 32 + a_row;
        float f[8] = {pre[i][0].x, pre[i][0].y, pre[i][0].z, pre[i][0].w,
                      pre[i][1].x, pre[i][1].y, pre[i][1].z, pre[i][1].w};
        __half h[8], l[8];
#pragma unroll
        for (int e = 0; e < 8; e++) {
            h[e] = __float2half_rn(f[e]);
            l[e] = __float2half_rn(f[e] - __half2float(h[e]));
        }
        uint32_t sw = SWZA(r, a_c8 * 8);
        *(uint4*)(smem + SM_AST + sw)         = *(uint4*)h;
        *(uint4*)(smem + SM_AST + 16384 + sw) = *(uint4*)l;
    }
    cp_async_wait_all();
    __syncthreads();

    float acc[2][4][4];
#pragma unroll
    for (int i = 0; i < 2; i++)
#pragma unroll
        for (int j = 0; j < 4; j++)
#pragma unroll
            for (int k = 0; k < 4; k++) acc[i][j][k] = 0.f;

    const int a_r  = (lane & 15);
    const int a_k8 = (lane >> 4) << 3;
    const int b_r  = (lane & 7) + ((lane >> 4) << 3);
    const int b_k8 = ((lane >> 3) & 1) << 3;

    for (int kc = 0; kc < 4; ++kc) {
        // prefetch next A chunk (LDG latency hides under MMA below)
        if (kc < 3) {
#pragma unroll
            for (int i = 0; i < 4; i++) {
                int r = i * 32 + a_row;
                const float* ga = A + (size_t)(m0 + r) * 256 + (kc + 1) * 64 + a_c8 * 8;
                pre[i][0] = *(const float4*)(ga);
                pre[i][1] = *(const float4*)(ga + 4);
            }
        }

        const uint32_t Ahb = sb + SM_AST + (kc & 1) * 32768;
        const uint32_t Alb = Ahb + 16384;
#pragma unroll
        for (int ks = 0; ks < 4; ++ks) {
            const int k0 = ks * 16;
            uint32_t ah[2][4], al[2][4], bh[2][4], bl[2][4];
#pragma unroll
            for (int mi = 0; mi < 2; mi++) {
                int r = wm + mi * 16 + a_r;
                uint32_t sw = SWZA(r, k0 + a_k8);
                ldmatrix_x4(ah[mi][0], ah[mi][1], ah[mi][2], ah[mi][3], Ahb + sw);
                ldmatrix_x4(al[mi][0], al[mi][1], al[mi][2], al[mi][3], Alb + sw);
            }
#pragma unroll
            for (int np = 0; np < 2; np++) {
                int r = wn + np * 16 + b_r;
                uint32_t sw = SWZB(r, kc * 64 + k0 + b_k8);
                ldmatrix_x4(bh[np][0], bh[np][1], bh[np][2], bh[np][3], sb + sw);
                ldmatrix_x4(bl[np][0], bl[np][1], bl[np][2], bl[np][3], sb + SM_BL + sw);
            }
#pragma unroll
            for (int mi = 0; mi < 2; mi++)
#pragma unroll
                for (int ni = 0; ni < 4; ni++) {
                    uint32_t h0 = bh[ni >> 1][(ni & 1) * 2], h1 = bh[ni >> 1][(ni & 1) * 2 + 1];
                    uint32_t l0 = bl[ni >> 1][(ni & 1) * 2], l1 = bl[ni >> 1][(ni & 1) * 2 + 1];
                    mma16816(acc[mi][ni], ah[mi], h0, h1);   // hh
                    mma16816(acc[mi][ni], ah[mi], l0, l1);   // hl
                    mma16816(acc[mi][ni], al[mi], h0, h1);   // lh
                }
        }

        // convert prefetched chunk -> other stage
        if (kc < 3) {
            uint32_t dst = sb + SM_AST + ((kc + 1) & 1) * 32768;
#pragma unroll
            for (int i = 0; i < 4; i++) {
                int r = i * 32 + a_row;
                float f[8] = {pre[i][0].x, pre[i][0].y, pre[i][0].z, pre[i][0].w,
                              pre[i][1].x, pre[i][1].y, pre[i][1].z, pre[i][1].w};
                __half h[8], l[8];
#pragma unroll
                for (int e = 0; e < 8; e++) {
                    h[e] = __float2half_rn(f[e]);
                    l[e] = __float2half_rn(f[e] - __half2float(h[e]));
                }
                uint32_t sw = SWZA(r, a_c8 * 8);
                *(uint4*)(smem + (dst - sb) + sw)         = *(uint4*)h;
                *(uint4*)(smem + (dst - sb) + 16384 + sw) = *(uint4*)l;
            }
        }
        __syncthreads();
    }

    // ---- epilogue ----
    const int g  = lane >> 2;
    const int tq = lane & 3;
#pragma unroll
    for (int ni = 0; ni < 4; ni++) {
        int c = n0 + wn + ni * 8 + 2 * tq;
        float bv0 = (c     < bsplit) ? bias0[c]     : bias1[c - bsplit];
        float bv1 = (c + 1 < bsplit) ? bias0[c + 1] : bias1[c + 1 - bsplit];
#pragma unroll
        for (int mi = 0; mi < 2; mi++) {
            int row = m0 + wm + mi * 16 + g;
            *(float2*)(C + (size_t)row * 256 + c)       = make_float2(acc[mi][ni][0] + bv0,
                                                                      acc[mi][ni][1] + bv1);
            *(float2*)(C + (size_t)(row + 8) * 256 + c) = make_float2(acc[mi][ni][2] + bv0,
                                                                      acc[mi][ni][3] + bv1);
        }
    }
}

// ---------------- fused weight prep: transpose + fp16 hi/lo split, all 4 matrices ----------------
__global__ void wprep_kernel(const float* __restrict__ W_val, const float* __restrict__ W_off,
                             const float* __restrict__ W_attn, const float* __restrict__ W_out,
                             __half* __restrict__ gwh, __half* __restrict__ gwl)
{
    int idx = blockIdx.x * blockDim.x + threadIdx.x;   // 0 .. 4*65536-1
    int mat = idx >> 16;
    int i   = idx & 65535;
    int n = i >> 8, k = i & 255;

    float x;
    int dst;
    if (mat == 0) {                 // W_val^T -> slot 0
        x = W_val[(size_t)k * 256 + n];
        dst = i;
    } else if (mat == 1) {          // W_off^T -> slot 1 rows [0,128)
        if (n >= 128) return;
        x = W_off[(size_t)k * 128 + n];
        dst = 65536 + n * 256 + k;
    } else if (mat == 2) {          // W_attn^T -> slot 1 rows [128,256)
        if (n >= 128) return;
        x = W_attn[(size_t)k * 128 + n];
        dst = 65536 + (128 + n) * 256 + k;
    } else {                        // W_out^T -> slot 3
        x = W_out[(size_t)k * 256 + n];
        dst = 3 * 65536 + i;
    }
    __half h = __float2half_rn(x);
    gwh[dst] = h;
    gwl[dst] = __float2half_rn(x - __half2float(h));
}

// ---------------- fused loc/softmax + bilinear sampling ----------------
// one warp per (nq, m). lanes 0-15: loc; lanes 16-31: softmaxed attn.
__global__ void sample_kernel(const float* __restrict__ value,
                              const float* __restrict__ goa,
                              const float* __restrict__ refp,
                              float* __restrict__ loc_out,
                              float* __restrict__ attn_out,
                              float* __restrict__ outv)
{
    int warp = (blockIdx.x * blockDim.x + threadIdx.x) >> 5;
    int lane = threadIdx.x & 31;
    if (warp >= NQ * 8) return;
    int m  = warp & 7;
    int nq = warp >> 3;
    int n  = nq >> 11;
    int j  = lane & 15;

    float v = goa[(size_t)nq * 256 + (lane < 16 ? m * 16 + j : 128 + m * 16 + j)];

    // softmax within the upper 16-lane half (lower-half result unused)
    float mx = v;
#pragma unroll
    for (int o = 1; o < 16; o <<= 1) mx = fmaxf(mx, __shfl_xor_sync(0xffffffffu, mx, o));
    float e = __expf(v - mx);
    float s = e;
#pragma unroll
    for (int o = 1; o < 16; o <<= 1) s += __shfl_xor_sync(0xffffffffu, s, o);

    int l4 = j >> 2;
    float myv = (lane < 16) ? (refp[(size_t)nq * 4 + l4] + v * c_invT[l4]) : (e / s);

    if (lane < 16) loc_out[(size_t)warp * 16 + j]  = myv;
    else           attn_out[(size_t)warp * 16 + j] = myv;

    float acc = 0.f;
    const float* vbase = value + (size_t)n * Ssum * 256 + m * 32 + lane;

#pragma unroll
    for (int lp = 0; lp < 16; ++lp) {
        float lv = __shfl_sync(0xffffffffu, myv, lp);        // loc
        float w  = __shfl_sync(0xffffffffu, myv, 16 + lp);   // attn weight
        int l = lp >> 2;
        int T = c_T[l];
        float pos  = lv * (float)T - 0.5f;
        float x0f  = floorf(pos);
        float frac = pos - x0f;
        int x0 = (int)x0f;
        float w0 = (x0 >= 0 && x0 < T) ? (1.f - frac) : 0.f;
        float w1 = (x0 + 1 >= 0 && x0 + 1 < T) ? frac : 0.f;
        if (w0 != 0.f || w1 != 0.f) {
            int i0 = min(max(x0, 0), T - 1);
            int i1 = min(max(x0 + 1, 0), T - 1);
            const float* p = vbase + (size_t)c_S[l] * 256;
            float v0 = p[(size_t)i0 * 256];
            float v1 = p[(size_t)i1 * 256];
            acc += w * (w0 * v0 + w1 * v1);
        }
    }
    outv[(size_t)warp * 32 + lane] = acc;
}

// ---------------- launch ----------------
extern "C" void kernel_launch(void* const* d_in, const int* in_sizes, int n_in,
                              void* d_out, int out_size)
{
    const float* query         = (const float*)d_in[0];
    const float* refpts        = (const float*)d_in[1];
    const float* input_flatten = (const float*)d_in[2];
    const float* W_off  = (const float*)d_in[5];
    const float* b_off  = (const float*)d_in[6];
    const float* W_attn = (const float*)d_in[7];
    const float* b_attn = (const float*)d_in[8];
    const float* W_val  = (const float*)d_in[9];
    const float* b_val  = (const float*)d_in[10];
    const float* W_out  = (const float*)d_in[11];
    const float* b_out  = (const float*)d_in[12];
    float* out = (float*)d_out;

    float *gv, *goa, *gt, *gls, *gas;
    __half *gwh, *gwl;
    cudaGetSymbolAddress((void**)&gv,  g_value);
    cudaGetSymbolAddress((void**)&goa, g_offattn);
    cudaGetSymbolAddress((void**)&gt,  g_tmp);
    cudaGetSymbolAddress((void**)&gwh, g_wh);
    cudaGetSymbolAddress((void**)&gwl, g_wl);
    cudaGetSymbolAddress((void**)&gls, g_loc_s);
    cudaGetSymbolAddress((void**)&gas, g_attn_s);

    const int OUT_ELEMS  = NQ * Cc;       // 4194304
    const int LOCA_ELEMS = NQ * 8 * 16;   // 2097152
    float* loc_out  = (out_size >= OUT_ELEMS + 2 * LOCA_ELEMS) ? out + OUT_ELEMS : gls;
    float* attn_out = (out_size >= OUT_ELEMS + 2 * LOCA_ELEMS) ? out + OUT_ELEMS + LOCA_ELEMS : gas;

    const int SMEM = 131072;  // 64 KB B + 2x32 KB A stages
    cudaFuncSetAttribute(hgemm_kernel, cudaFuncAttributeMaxDynamicSharedMemorySize, SMEM);

    __half* wvh = gwh;               __half* wvl = gwl;                // W_val^T
    __half* wqh = gwh + 1 * Cc * Cc; __half* wql = gwl + 1 * Cc * Cc;  // [W_off;W_attn]^T
    __half* woh = gwh + 3 * Cc * Cc; __half* wol = gwl + 3 * Cc * Cc;  // W_out^T

    // 1. weight transpose + split (one launch)
    wprep_kernel<<<(4 * 65536) / 256, 256>>>(W_val, W_off, W_attn, W_out, gwh, gwl);

    // 2. fused: value projection (240 blocks) + off/attn projection (128 blocks), grid.y = 4 N-tiles
    hgemm_kernel<<<dim3(NROWS_VAL / 128 + NQ / 128, 4), 256, SMEM>>>(
        input_flatten, wvh, wvl, b_val, b_val, 512, gv, NROWS_VAL / 128,
        query,         wqh, wql, b_off, b_attn, 128, goa);

    // 3. fused loc/softmax + deformable sampling -> fp32 tmp (also outputs loc & attn)
    sample_kernel<<<(NQ * 8) / 8, 256>>>(gv, goa, refpts, loc_out, attn_out, gt);

    // 4. output projection -> d_out
    hgemm_kernel<<<dim3(NQ / 128, 4), 256, SMEM>>>(
        gt, woh, wol, b_out, b_out, 512, out, NQ / 128,
        gt, woh, wol, b_out, b_out, 512, out);
}

// round 10
// speedup vs baseline: 1.9312x; 1.0389x over previous
#include <cuda_runtime.h>
#include <cuda_fp16.h>
#include <cstdint>

// ---------------- problem constants ----------------
#define Nb   8
#define LQ   2048
#define Cc   256
#define NQ   (Nb*LQ)        // 16384
#define Ssum 3840
#define NROWS_VAL (Nb*Ssum) // 30720

__device__ __constant__ int   c_T[4]    = {2048, 1024, 512, 256};
__device__ __constant__ int   c_S[4]    = {0, 2048, 3072, 3584};
__device__ __constant__ float c_invT[4] = {1.f/2048.f, 1.f/1024.f, 1.f/512.f, 1.f/256.f};

// ---------------- static scratch ----------------
__device__ float  g_value[NROWS_VAL * Cc];      // fp32 value projection (31.5 MB)
__device__ float  g_offattn[NQ * Cc];           // off logits (0-127) + attn logits (128-255)
__device__ float  g_tmp[NQ * Cc];               // sampled tensor (feeds out-proj)
__device__ __half g_wh[4][Cc * Cc];             // transposed weight hi: 0=val, 1,2=off||attn, 3=out
__device__ __half g_wl[4][Cc * Cc];
__device__ float  g_loc_s[NQ * 8 * 16];
__device__ float  g_attn_s[NQ * 8 * 16];

// ---------------- helpers ----------------
__device__ __forceinline__ uint32_t smem_u32(const void* p) {
    uint32_t a;
    asm("{ .reg .u64 t; cvta.to.shared.u64 t, %1; cvt.u32.u64 %0, t; }" : "=r"(a) : "l"(p));
    return a;
}
__device__ __forceinline__ void ldmatrix_x4(uint32_t& r0, uint32_t& r1, uint32_t& r2, uint32_t& r3,
                                            uint32_t addr) {
    asm volatile("ldmatrix.sync.aligned.m8n8.x4.shared.b16 {%0,%1,%2,%3}, [%4];"
                 : "=r"(r0), "=r"(r1), "=r"(r2), "=r"(r3) : "r"(addr));
}
__device__ __forceinline__ void mma16816(float* c, const uint32_t* a, uint32_t b0, uint32_t b1) {
    asm volatile("mma.sync.aligned.m16n8k16.row.col.f32.f16.f16.f32 "
                 "{%0,%1,%2,%3},{%4,%5,%6,%7},{%8,%9},{%0,%1,%2,%3};"
                 : "+f"(c[0]), "+f"(c[1]), "+f"(c[2]), "+f"(c[3])
                 : "r"(a[0]), "r"(a[1]), "r"(a[2]), "r"(a[3]), "r"(b0), "r"(b1));
}
__device__ __forceinline__ void cp_async16(uint32_t dst, const void* src) {
    asm volatile("cp.async.cg.shared.global [%0], [%1], 16;" :: "r"(dst), "l"(src));
}
__device__ __forceinline__ void cp_async_wait_all() {
    asm volatile("cp.async.commit_group;\n\tcp.async.wait_group 0;" ::: "memory");
}

// B resident tile: 64 rows x 256 halfs (512 B/row); chunk-XOR swizzle (low 3 bits of chunk)
#define SWZB(r, k) ((r) * 512 + ((((((k) >> 3) & ~7) | ((((k) >> 3) & 7) ^ ((r) & 7)))) << 4))
// A stage: 128 rows x 32 halfs (64 B/row); 4 chunks/row, XOR by (r>>1)&3 (conflict-free for ldsm)
#define SWZA32(r, k) ((r) * 64 + (((((k) >> 3) & 3) ^ (((r) >> 1) & 3)) << 4))

// smem layout (bytes): Bh [0,32K) | Bl [32K,64K) | A stages: 64K + s*16K (Ah 8K, Al 8K)
#define SM_BL  32768
#define SM_AST 65536
#define SM_TOT 98304

// ---------------- pipelined HMMA GEMM, 2 CTAs/SM, fused fp32->fp16 hi/lo split of A ----------
// C[M x 256] = A[M,256] @ Bt[256,256]^T + bias.  3-term compensated (hh + hl + lh), fp32 acc.
// Block 128(m) x 64(n); 8 warps = 4m x 2n, warp tile 32x32. K: 8 pipelined chunks of 32.
// Dual dispatch: blocks [0,nx0) run problem 0, rest run problem 1.
__global__ __launch_bounds__(256, 2)
void hgemm_kernel(const float* __restrict__ A0, const __half* __restrict__ B0h,
                  const __half* __restrict__ B0l, const float* __restrict__ b0a,
                  const float* __restrict__ b0b, int bsplit0, float* __restrict__ C0, int nx0,
                  const float* __restrict__ A1, const __half* __restrict__ B1h,
                  const __half* __restrict__ B1l, const float* __restrict__ b1a,
                  const float* __restrict__ b1b, int bsplit1, float* __restrict__ C1)
{
    extern __shared__ char smem[];
    const uint32_t sb = smem_u32(smem);
    const int tid = threadIdx.x;
    const int wid = tid >> 5;
    const int lane = tid & 31;

    const bool p0 = ((int)blockIdx.x < nx0);
    const float*  A      = p0 ? A0 : A1;
    const __half* Bh     = p0 ? B0h : B1h;
    const __half* Bl     = p0 ? B0l : B1l;
    const float*  bias0  = p0 ? b0a : b1a;
    const float*  bias1  = p0 ? b0b : b1b;
    const int     bsplit = p0 ? bsplit0 : bsplit1;
    float*        C      = p0 ? C0 : C1;
    const int m0 = (p0 ? blockIdx.x : blockIdx.x - nx0) * 128;
    const int n0 = blockIdx.y * 64;
    const int wm = (wid & 3) * 32;
    const int wn = (wid >> 2) * 32;

    // ---- B resident load (once): 64 rows x 256 k, hi+lo, via cp.async ----
#pragma unroll
    for (int i = 0; i < 8; i++) {
        int lin = i * 256 + tid;                 // 0..2047
        int r = lin >> 5, c = lin & 31;          // row, 16B-chunk
        size_t g = (size_t)(n0 + r) * 256 + c * 8;
        uint32_t sw = SWZB(r, c * 8);
        cp_async16(sb + sw,         Bh + g);
        cp_async16(sb + SM_BL + sw, Bl + g);
    }

    // ---- A loader mapping: thread t -> row tid>>1, 16-half half (tid&1) of the 32-wide chunk ----
    const int a_r0   = tid >> 1;
    const int a_half = tid & 1;
    const float* Abase = A + (size_t)(m0 + a_r0) * 256 + a_half * 16;

    float4 pre[4];
#pragma unroll
    for (int i = 0; i < 4; i++) pre[i] = *(const float4*)(Abase + i * 4);

    // convert chunk 0 -> stage 0
    {
        float f[16] = {pre[0].x, pre[0].y, pre[0].z, pre[0].w, pre[1].x, pre[1].y, pre[1].z, pre[1].w,
                       pre[2].x, pre[2].y, pre[2].z, pre[2].w, pre[3].x, pre[3].y, pre[3].z, pre[3].w};
        __half h[16], l[16];
#pragma unroll
        for (int e = 0; e < 16; e++) {
            h[e] = __float2half_rn(f[e]);
            l[e] = __float2half_rn(f[e] - __half2float(h[e]));
        }
#pragma unroll
        for (int j = 0; j < 2; j++) {
            uint32_t sw = (uint32_t)(a_r0 * 64 + (((a_half * 2 + j) ^ ((a_r0 >> 1) & 3)) << 4));
            *(uint4*)(smem + SM_AST + sw)        = ((uint4*)h)[j];
            *(uint4*)(smem + SM_AST + 8192 + sw) = ((uint4*)l)[j];
        }
    }
    cp_async_wait_all();
    __syncthreads();

    float acc[2][4][4];
#pragma unroll
    for (int i = 0; i < 2; i++)
#pragma unroll
        for (int j = 0; j < 4; j++)
#pragma unroll
            for (int k = 0; k < 4; k++) acc[i][j][k] = 0.f;

    const int a_r  = (lane & 15);
    const int a_k8 = (lane >> 4) << 3;
    const int b_r  = (lane & 7) + ((lane >> 4) << 3);
    const int b_k8 = ((lane >> 3) & 1) << 3;

    for (int kc = 0; kc < 8; ++kc) {
        // prefetch next A chunk (hidden under MMAs below)
        if (kc < 7) {
#pragma unroll
            for (int i = 0; i < 4; i++)
                pre[i] = *(const float4*)(Abase + (kc + 1) * 32 + i * 4);
        }

        const uint32_t Ahb = sb + SM_AST + (kc & 1) * 16384;
        const uint32_t Alb = Ahb + 8192;
#pragma unroll
        for (int ks = 0; ks < 2; ++ks) {
            const int k0 = ks * 16;
            uint32_t ah[2][4], al[2][4], bh[2][4], bl[2][4];
#pragma unroll
            for (int mi = 0; mi < 2; mi++) {
                int r = wm + mi * 16 + a_r;
                uint32_t sw = SWZA32(r, k0 + a_k8);
                ldmatrix_x4(ah[mi][0], ah[mi][1], ah[mi][2], ah[mi][3], Ahb + sw);
                ldmatrix_x4(al[mi][0], al[mi][1], al[mi][2], al[mi][3], Alb + sw);
            }
#pragma unroll
            for (int np = 0; np < 2; np++) {
                int r = wn + np * 16 + b_r;
                uint32_t sw = SWZB(r, kc * 32 + k0 + b_k8);
                ldmatrix_x4(bh[np][0], bh[np][1], bh[np][2], bh[np][3], sb + sw);
                ldmatrix_x4(bl[np][0], bl[np][1], bl[np][2], bl[np][3], sb + SM_BL + sw);
            }
#pragma unroll
            for (int mi = 0; mi < 2; mi++)
#pragma unroll
                for (int ni = 0; ni < 4; ni++) {
                    uint32_t h0 = bh[ni >> 1][(ni & 1) * 2], h1 = bh[ni >> 1][(ni & 1) * 2 + 1];
                    uint32_t l0 = bl[ni >> 1][(ni & 1) * 2], l1 = bl[ni >> 1][(ni & 1) * 2 + 1];
                    mma16816(acc[mi][ni], ah[mi], h0, h1);   // hh
                    mma16816(acc[mi][ni], ah[mi], l0, l1);   // hl
                    mma16816(acc[mi][ni], al[mi], h0, h1);   // lh
                }
        }

        // convert prefetched chunk -> other stage (safe: other stage idle since last sync)
        if (kc < 7) {
            uint32_t dst = SM_AST + ((kc + 1) & 1) * 16384;
            float f[16] = {pre[0].x, pre[0].y, pre[0].z, pre[0].w, pre[1].x, pre[1].y, pre[1].z, pre[1].w,
                           pre[2].x, pre[2].y, pre[2].z, pre[2].w, pre[3].x, pre[3].y, pre[3].z, pre[3].w};
            __half h[16], l[16];
#pragma unroll
            for (int e = 0; e < 16; e++) {
                h[e] = __float2half_rn(f[e]);
                l[e] = __float2half_rn(f[e] - __half2float(h[e]));
            }
#pragma unroll
            for (int j = 0; j < 2; j++) {
                uint32_t sw = (uint32_t)(a_r0 * 64 + (((a_half * 2 + j) ^ ((a_r0 >> 1) & 3)) << 4));
                *(uint4*)(smem + dst + sw)        = ((uint4*)h)[j];
                *(uint4*)(smem + dst + 8192 + sw) = ((uint4*)l)[j];
            }
        }
        __syncthreads();
    }

    // ---- epilogue ----
    const int g  = lane >> 2;
    const int tq = lane & 3;
#pragma unroll
    for (int ni = 0; ni < 4; ni++) {
        int c = n0 + wn + ni * 8 + 2 * tq;
        float bv0 = (c     < bsplit) ? bias0[c]     : bias1[c - bsplit];
        float bv1 = (c + 1 < bsplit) ? bias0[c + 1] : bias1[c + 1 - bsplit];
#pragma unroll
        for (int mi = 0; mi < 2; mi++) {
            int row = m0 + wm + mi * 16 + g;
            *(float2*)(C + (size_t)row * 256 + c)       = make_float2(acc[mi][ni][0] + bv0,
                                                                      acc[mi][ni][1] + bv1);
            *(float2*)(C + (size_t)(row + 8) * 256 + c) = make_float2(acc[mi][ni][2] + bv0,
                                                                      acc[mi][ni][3] + bv1);
        }
    }
}

// ---------------- fused weight prep: transpose + fp16 hi/lo split, all 4 matrices ----------------
__global__ void wprep_kernel(const float* __restrict__ W_val, const float* __restrict__ W_off,
                             const float* __restrict__ W_attn, const float* __restrict__ W_out,
                             __half* __restrict__ gwh, __half* __restrict__ gwl)
{
    int idx = blockIdx.x * blockDim.x + threadIdx.x;   // 0 .. 4*65536-1
    int mat = idx >> 16;
    int i   = idx & 65535;
    int n = i >> 8, k = i & 255;

    float x;
    int dst;
    if (mat == 0) {                 // W_val^T -> slot 0
        x = W_val[(size_t)k * 256 + n];
        dst = i;
    } else if (mat == 1) {          // W_off^T -> slot 1 rows [0,128)
        if (n >= 128) return;
        x = W_off[(size_t)k * 128 + n];
        dst = 65536 + n * 256 + k;
    } else if (mat == 2) {          // W_attn^T -> slot 1 rows [128,256)
        if (n >= 128) return;
        x = W_attn[(size_t)k * 128 + n];
        dst = 65536 + (128 + n) * 256 + k;
    } else {                        // W_out^T -> slot 3
        x = W_out[(size_t)k * 256 + n];
        dst = 3 * 65536 + i;
    }
    __half h = __float2half_rn(x);
    gwh[dst] = h;
    gwl[dst] = __float2half_rn(x - __half2float(h));
}

// ---------------- fused loc/softmax + bilinear sampling ----------------
// one warp per (nq, m). lanes 0-15: loc; lanes 16-31: softmaxed attn.
__global__ void sample_kernel(const float* __restrict__ value,
                              const float* __restrict__ goa,
                              const float* __restrict__ refp,
                              float* __restrict__ loc_out,
                              float* __restrict__ attn_out,
                              float* __restrict__ outv)
{
    int warp = (blockIdx.x * blockDim.x + threadIdx.x) >> 5;
    int lane = threadIdx.x & 31;
    if (warp >= NQ * 8) return;
    int m  = warp & 7;
    int nq = warp >> 3;
    int n  = nq >> 11;
    int j  = lane & 15;

    float v = goa[(size_t)nq * 256 + (lane < 16 ? m * 16 + j : 128 + m * 16 + j)];

    // softmax within the upper 16-lane half (lower-half result unused)
    float mx = v;
#pragma unroll
    for (int o = 1; o < 16; o <<= 1) mx = fmaxf(mx, __shfl_xor_sync(0xffffffffu, mx, o));
    float e = __expf(v - mx);
    float s = e;
#pragma unroll
    for (int o = 1; o < 16; o <<= 1) s += __shfl_xor_sync(0xffffffffu, s, o);

    int l4 = j >> 2;
    float myv = (lane < 16) ? (refp[(size_t)nq * 4 + l4] + v * c_invT[l4]) : (e / s);

    if (lane < 16) loc_out[(size_t)warp * 16 + j]  = myv;
    else           attn_out[(size_t)warp * 16 + j] = myv;

    float acc = 0.f;
    const float* vbase = value + (size_t)n * Ssum * 256 + m * 32 + lane;

#pragma unroll
    for (int lp = 0; lp < 16; ++lp) {
        float lv = __shfl_sync(0xffffffffu, myv, lp);        // loc
        float w  = __shfl_sync(0xffffffffu, myv, 16 + lp);   // attn weight
        int l = lp >> 2;
        int T = c_T[l];
        float pos  = lv * (float)T - 0.5f;
        float x0f  = floorf(pos);
        float frac = pos - x0f;
        int x0 = (int)x0f;
        float w0 = (x0 >= 0 && x0 < T) ? (1.f - frac) : 0.f;
        float w1 = (x0 + 1 >= 0 && x0 + 1 < T) ? frac : 0.f;
        if (w0 != 0.f || w1 != 0.f) {
            int i0 = min(max(x0, 0), T - 1);
            int i1 = min(max(x0 + 1, 0), T - 1);
            const float* p = vbase + (size_t)c_S[l] * 256;
            float v0 = p[(size_t)i0 * 256];
            float v1 = p[(size_t)i1 * 256];
            acc += w * (w0 * v0 + w1 * v1);
        }
    }
    outv[(size_t)warp * 32 + lane] = acc;
}

// ---------------- launch ----------------
extern "C" void kernel_launch(void* const* d_in, const int* in_sizes, int n_in,
                              void* d_out, int out_size)
{
    const float* query         = (const float*)d_in[0];
    const float* refpts        = (const float*)d_in[1];
    const float* input_flatten = (const float*)d_in[2];
    const float* W_off  = (const float*)d_in[5];
    const float* b_off  = (const float*)d_in[6];
    const float* W_attn = (const float*)d_in[7];
    const float* b_attn = (const float*)d_in[8];
    const float* W_val  = (const float*)d_in[9];
    const float* b_val  = (const float*)d_in[10];
    const float* W_out  = (const float*)d_in[11];
    const float* b_out  = (const float*)d_in[12];
    float* out = (float*)d_out;

    float *gv, *goa, *gt, *gls, *gas;
    __half *gwh, *gwl;
    cudaGetSymbolAddress((void**)&gv,  g_value);
    cudaGetSymbolAddress((void**)&goa, g_offattn);
    cudaGetSymbolAddress((void**)&gt,  g_tmp);
    cudaGetSymbolAddress((void**)&gwh, g_wh);
    cudaGetSymbolAddress((void**)&gwl, g_wl);
    cudaGetSymbolAddress((void**)&gls, g_loc_s);
    cudaGetSymbolAddress((void**)&gas, g_attn_s);

    const int OUT_ELEMS  = NQ * Cc;       // 4194304
    const int LOCA_ELEMS = NQ * 8 * 16;   // 2097152
    float* loc_out  = (out_size >= OUT_ELEMS + 2 * LOCA_ELEMS) ? out + OUT_ELEMS : gls;
    float* attn_out = (out_size >= OUT_ELEMS + 2 * LOCA_ELEMS) ? out + OUT_ELEMS + LOCA_ELEMS : gas;

    cudaFuncSetAttribute(hgemm_kernel, cudaFuncAttributeMaxDynamicSharedMemorySize, SM_TOT);

    __half* wvh = gwh;               __half* wvl = gwl;                // W_val^T
    __half* wqh = gwh + 1 * Cc * Cc; __half* wql = gwl + 1 * Cc * Cc;  // [W_off;W_attn]^T
    __half* woh = gwh + 3 * Cc * Cc; __half* wol = gwl + 3 * Cc * Cc;  // W_out^T

    // 1. weight transpose + split (one launch)
    wprep_kernel<<<(4 * 65536) / 256, 256>>>(W_val, W_off, W_attn, W_out, gwh, gwl);

    // 2. fused: value projection (240 blocks) + off/attn projection (128 blocks), grid.y = 4
    hgemm_kernel<<<dim3(NROWS_VAL / 128 + NQ / 128, 4), 256, SM_TOT>>>(
        input_flatten, wvh, wvl, b_val, b_val, 512, gv, NROWS_VAL / 128,
        query,         wqh, wql, b_off, b_attn, 128, goa);

    // 3. fused loc/softmax + deformable sampling -> fp32 tmp (also outputs loc & attn)
    sample_kernel<<<(NQ * 8) / 8, 256>>>(gv, goa, refpts, loc_out, attn_out, gt);

    // 4. output projection -> d_out
    hgemm_kernel<<<dim3(NQ / 128, 4), 256, SM_TOT>>>(
        gt, woh, wol, b_out, b_out, 512, out, NQ / 128,
        gt, woh, wol, b_out, b_out, 512, out);
}